// round 11
// baseline (speedup 1.0000x reference)
#include <cuda_runtime.h>
#include <cuda_fp16.h>
#include <cstdint>

// ============================================================================
// IndRNN on GB300 — single warp-specialized persistent kernel.
//   128 CTAs = 4 n-blocks x 32 batch-pairs, 512 threads, occ 1 (single wave).
//   Roles: warps 0-7 COMPUTE (32x64 tiles, HMMA fp16->fp32),
//          warps 8-11 A-PRODUCER (LDG x fp32 -> cvt fp16 -> STS ring),
//          warps 12-15 SCAN (full-tile scan + coalesced STG).
//   B = W^T fp16 fully resident in smem (converted once at init by all).
//   Named-barrier producer/consumer handshakes; phases fully overlapped.
// Shapes: B=64, T=512, D(K)=256, U(N)=512. rel_err ~2.35e-4 (same roundings).
// ============================================================================

#define U_DIM 512
#define K_DIM 256
#define T_DIM 512
#define NT 128
#define ROWB 80                    // padded row stride: conflict-free ldmatrix
#define SUBT (128 * ROWB)          // one 128x32 fp16 subtile: 10240 B
#define A_BASE 0                   // 4-stage A ring: 40960 B
#define B_BASE (4 * SUBT)          // B full K: 8 subtiles: 81920 B
#define SC_BASE (12 * SUBT)        // scan buffer
#define SCROW 130
#define SCBYTES (128 * SCROW * 4)  // 66560 B
#define SMEM_BYTES (12 * SUBT + SCBYTES)   // 189440 B -> occ 1

// ---------------------------------------------------------------- helpers
__device__ __forceinline__ uint32_t smem_u32(const void* p) {
    uint32_t a;
    asm("{ .reg .u64 t; cvta.to.shared.u64 t, %1; cvt.u32.u64 %0, t; }"
        : "=r"(a) : "l"(p));
    return a;
}
__device__ __forceinline__ void ldsm_x4(uint32_t* r, uint32_t addr) {
    asm volatile("ldmatrix.sync.aligned.m8n8.x4.shared.b16 {%0,%1,%2,%3}, [%4];"
                 : "=r"(r[0]), "=r"(r[1]), "=r"(r[2]), "=r"(r[3]) : "r"(addr));
}
__device__ __forceinline__ void mma_f16(float* c, const uint32_t* a,
                                        uint32_t b0, uint32_t b1) {
    asm volatile(
        "mma.sync.aligned.m16n8k16.row.col.f32.f16.f16.f32 "
        "{%0,%1,%2,%3}, {%4,%5,%6,%7}, {%8,%9}, {%0,%1,%2,%3};"
        : "+f"(c[0]), "+f"(c[1]), "+f"(c[2]), "+f"(c[3])
        : "r"(a[0]), "r"(a[1]), "r"(a[2]), "r"(a[3]), "r"(b0), "r"(b1));
}
#define NB_SYNC(id, cnt)   asm volatile("bar.sync %0, %1;"   :: "r"(id), "r"(cnt) : "memory")
#define NB_ARRIVE(id, cnt) asm volatile("bar.arrive %0, %1;" :: "r"(id), "r"(cnt) : "memory")

__device__ __forceinline__ uint32_t pack_h2(__half a, __half b) {
    __half2 p(a, b);
    return *reinterpret_cast<uint32_t*>(&p);
}
__device__ __forceinline__ void sts_round4(float4 v, uint32_t dst) {
    __half hx = __float2half_rn(v.x), hy = __float2half_rn(v.y);
    __half hz = __float2half_rn(v.z), hw = __float2half_rn(v.w);
    asm volatile("st.shared.v2.b32 [%0], {%1, %2};"
                 :: "r"(dst), "r"(pack_h2(hx, hy)), "r"(pack_h2(hz, hw)) : "memory");
}
__device__ __forceinline__ void sts16(uint32_t dst, uint32_t v) {
    asm volatile("st.shared.b32 [%0], %1;" :: "r"(dst), "r"(v) : "memory");
}

// Barrier ids: full[s]=1+s (s=0..3), free[s]=5+s, scanfull=9, scanfree=10.
// All counts 384 (producer/consumer role pairs sum to 384 threads).

__global__ __launch_bounds__(512, 1)
void indrnn_ws_kernel(const float* __restrict__ W,     // [K, N] fp32
                      const float* __restrict__ X,     // [M, K] fp32
                      const float* __restrict__ bias,  // [N]
                      const float* __restrict__ h0g,   // [B, U]
                      const float* __restrict__ ug,    // [U]
                      float* __restrict__ C)           // [M, U_DIM]
{
    extern __shared__ char smem[];
    const uint32_t sb = smem_u32(smem);
    float* const scf = reinterpret_cast<float*>(smem + SC_BASE);

    const int tid  = threadIdx.x;
    const int lane = tid & 31;
    const int wid  = tid >> 5;
    const int n0   = blockIdx.x * NT;
    const int by   = blockIdx.y;          // batch pair index (0..31)

    // ---------------- init: ALL threads convert W^T (n0..n0+127, K) -> B smem
    // unit u: kp = u>>5 (k pair), nq = u&31 (n quad). 4096 units, 8/thread.
    #pragma unroll
    for (int i = 0; i < 8; i++) {
        int u  = i * 512 + tid;
        int k  = (u >> 5) * 2;
        int n  = (u & 31) * 4;
        float4 r0 = *reinterpret_cast<const float4*>(W + (size_t)k * U_DIM + n0 + n);
        float4 r1 = *reinterpret_cast<const float4*>(W + (size_t)(k + 1) * U_DIM + n0 + n);
        const float* p0 = &r0.x;
        const float* p1 = &r1.x;
        #pragma unroll
        for (int j = 0; j < 4; j++) {
            uint32_t v = pack_h2(__float2half_rn(p0[j]), __float2half_rn(p1[j]));
            uint32_t addr = sb + B_BASE + (uint32_t)((k >> 5) * SUBT
                              + (n + j) * ROWB + (k & 31) * 2);
            sts16(addr, v);
        }
    }
    __syncthreads();   // last full-block sync; roles diverge after this

    if (wid < 8) {
        // ================= COMPUTE warps (tids 0..255) =================
        const int wm = wid & 3;
        const int wn = wid >> 2;
        const uint32_t aOff = (uint32_t)((lane & 15) * ROWB + (lane >> 4) * 16);
        const uint32_t bOff = (uint32_t)(((lane & 7) + ((lane >> 4) & 1) * 8) * ROWB
                                         + ((lane >> 3) & 1) * 16);
        const int colBase = wn * 64 + (lane & 3) * 2;
        const int rowBase = wm * 32 + (lane >> 2);

        float2 bv[8];
        #pragma unroll
        for (int nt = 0; nt < 8; nt++)
            bv[nt] = *reinterpret_cast<const float2*>(bias + n0 + colBase + nt * 8);

        #pragma unroll 1
        for (int tc = 0; tc < 8; tc++) {
            float acc[2][8][4];
            #pragma unroll
            for (int mt = 0; mt < 2; mt++)
                #pragma unroll
                for (int nt = 0; nt < 8; nt++)
                    #pragma unroll
                    for (int q = 0; q < 4; q++)
                        acc[mt][nt][q] = 0.0f;

            #pragma unroll 1
            for (int c = 0; c < 8; c++) {
                const int g = tc * 8 + c;
                const int s = g & 3;
                NB_SYNC(1 + s, 384);                       // A chunk ready
                const uint32_t uA = sb + (uint32_t)(A_BASE + s * SUBT);
                const uint32_t uB = sb + (uint32_t)(B_BASE + c * SUBT);
                #pragma unroll
                for (int ks = 0; ks < 2; ks++) {
                    const uint32_t kb = ks * 32;
                    uint32_t ah[2][4];
                    #pragma unroll
                    for (int mt = 0; mt < 2; mt++)
                        ldsm_x4(ah[mt], uA + (uint32_t)((wm * 32 + mt * 16) * ROWB) + aOff + kb);
                    #pragma unroll
                    for (int np = 0; np < 4; np++) {
                        uint32_t bh[4];
                        ldsm_x4(bh, uB + (uint32_t)((wn * 64 + np * 16) * ROWB) + bOff + kb);
                        #pragma unroll
                        for (int mt = 0; mt < 2; mt++) {
                            mma_f16(acc[mt][np * 2 + 0], ah[mt], bh[0], bh[1]);
                            mma_f16(acc[mt][np * 2 + 1], ah[mt], bh[2], bh[3]);
                        }
                    }
                }
                NB_ARRIVE(5 + s, 384);                     // stage free
            }

            if (tc > 0) NB_SYNC(10, 384);                  // scan buffer free
            #pragma unroll
            for (int nt = 0; nt < 8; nt++) {
                const int col = colBase + nt * 8;
                #pragma unroll
                for (int mt = 0; mt < 2; mt++) {
                    const int r = rowBase + mt * 16;
                    float2 o0 = { acc[mt][nt][0] + bv[nt].x, acc[mt][nt][1] + bv[nt].y };
                    float2 o1 = { acc[mt][nt][2] + bv[nt].x, acc[mt][nt][3] + bv[nt].y };
                    *reinterpret_cast<float2*>(scf + (size_t)r * SCROW + col)       = o0;
                    *reinterpret_cast<float2*>(scf + (size_t)(r + 8) * SCROW + col) = o1;
                }
            }
            NB_ARRIVE(9, 384);                             // scan buffer full
        }
    } else if (wid < 12) {
        // ================= A-PRODUCER warps (tids 256..383) =================
        const int pt = tid - 256;                          // 0..127
        float4 rcur[8], rnxt[8];
        auto ldg_chunk = [&](int g, float4* r) {
            const int tc = g >> 3;
            const int b  = 2 * by + (tc >> 2);
            const int trow = (tc & 3) << 7;
            const int kk = (g & 7) << 5;
            const float* src = X + ((size_t)b * T_DIM + trow) * K_DIM + kk;
            #pragma unroll
            for (int i = 0; i < 8; i++) {
                int f = i * 128 + pt;
                r[i] = *reinterpret_cast<const float4*>(
                    src + (size_t)(f >> 3) * K_DIM + (f & 7) * 4);
            }
        };
        ldg_chunk(0, rcur);
        #pragma unroll 1
        for (int g = 0; g < 64; g++) {
            const int s = g & 3;
            if (g + 1 < 64) ldg_chunk(g + 1, rnxt);        // prefetch (MLP)
            if (g >= 4) NB_SYNC(5 + s, 384);               // stage free
            const uint32_t stb = sb + (uint32_t)(A_BASE + s * SUBT);
            #pragma unroll
            for (int i = 0; i < 8; i++) {
                int f = i * 128 + pt;
                sts_round4(rcur[i], stb + (uint32_t)((f >> 3) * ROWB + (f & 7) * 8));
            }
            NB_ARRIVE(1 + s, 384);                         // chunk ready
            #pragma unroll
            for (int i = 0; i < 8; i++) rcur[i] = rnxt[i];
        }
    } else {
        // ================= SCAN warps (tids 384..511) =================
        const int sc = tid - 384;                          // column 0..127
        const float uc = fminf(fmaxf(ug[n0 + sc], 0.0f), 1.0f);
        float h = 0.0f;
        #pragma unroll 1
        for (int tc = 0; tc < 8; tc++) {
            const int b = 2 * by + (tc >> 2);
            if ((tc & 3) == 0)
                h = h0g[(size_t)b * U_DIM + n0 + sc];
            NB_SYNC(9, 384);                               // scan buffer full
            float* crow = C + ((size_t)b * T_DIM + ((tc & 3) << 7)) * U_DIM + n0 + sc;
            #pragma unroll
            for (int t = 0; t < 128; t += 8) {
                float v[8];
                #pragma unroll
                for (int i = 0; i < 8; i++)
                    v[i] = scf[(size_t)(t + i) * SCROW + sc];
                #pragma unroll
                for (int i = 0; i < 8; i++) {
                    h = fmaxf(fmaf(h, uc, v[i]), 0.0f);
                    v[i] = h;
                }
                #pragma unroll
                for (int i = 0; i < 8; i++)
                    crow[(size_t)(t + i) * U_DIM] = v[i];
            }
            NB_ARRIVE(10, 384);                            // scan buffer free
        }
    }
}

// ---------------------------------------------------------------- launch
extern "C" void kernel_launch(void* const* d_in, const int* in_sizes, int n_in,
                              void* d_out, int out_size)
{
    const float* x  = (const float*)d_in[0];  // [B,T,D]
    const float* h0 = (const float*)d_in[1];  // [B,U]
    const float* W  = (const float*)d_in[2];  // [D,U]
    const float* u  = (const float*)d_in[3];  // [U]
    const float* bb = (const float*)d_in[4];  // [U]
    float* out = (float*)d_out;               // [B,T,U]

    const int U = in_sizes[3];                // 512
    const int B = in_sizes[1] / U;            // 64

    cudaFuncSetAttribute(indrnn_ws_kernel,
                         cudaFuncAttributeMaxDynamicSharedMemorySize, SMEM_BYTES);
    dim3 gg(U / NT, B / 2);   // (4, 32) = 128 CTAs, occ 1, single wave
    indrnn_ws_kernel<<<gg, 512, SMEM_BYTES>>>(W, x, bb, h0, u, out);
}

// round 12
// speedup vs baseline: 1.2162x; 1.2162x over previous
#include <cuda_runtime.h>
#include <cuda_fp16.h>
#include <cstdint>

// ============================================================================
// IndRNN on GB300 — prep (x->fp16, W^T->fp16) + fused GEMM/scan with
// TILE-LEVEL SOFTWARE PIPELINING:
//   While tile tc's 8 MMA chunks run, the previous tile's scan executes as 8
//   interleaved slices (16 timesteps each), alternating between warp groups
//   0-3 and 4-7 (scan state h lives in smem). Dump is the only serial phase.
//   2-stage cp.async ring (KC=32), 32x64 warp tiles, occ 2 (16 warps/SM).
// Shapes: B=64, T=512, D(K)=256, U(N)=512, M=B*T=32768
// rel_err ~ 2.35e-4 (identical fp16 roundings + fp32 accumulation to R8).
// ============================================================================

#define U_DIM 512
#define K_DIM 256
#define T_DIM 512
#define M_DIM 32768
#define MT 128
#define NT 128
#define KC 32
#define ROWB 80                        // 5*16: conflict-free ldmatrix
#define TSTG (128 * ROWB)              // one 128x32 fp16 tile: 10240 B
#define STG_B (2 * TSTG)               // A + B per stage: 20480 B
#define NSTAGE 2
#define STAGES_BYTES (NSTAGE * STG_B)  // 40960 B
#define SCROW 130
#define SCBYTES (128 * SCROW * 4)      // 66560 B (full tile)
#define SH_OFF  (STAGES_BYTES + SCBYTES)          // h state: 512 B
#define SU_OFF  (SH_OFF + 512)                    // u state: 512 B
#define SMEM_BYTES (SU_OFF + 512)                 // 108544 B -> occ 2

__device__ __half g_Wt[U_DIM * K_DIM];   // W^T [N][K] fp16
__device__ __half g_Xh[M_DIM * K_DIM];   // x   [M][K] fp16

// ---------------------------------------------------------------- helpers
__device__ __forceinline__ uint32_t smem_u32(const void* p) {
    uint32_t a;
    asm("{ .reg .u64 t; cvta.to.shared.u64 t, %1; cvt.u32.u64 %0, t; }"
        : "=r"(a) : "l"(p));
    return a;
}
__device__ __forceinline__ void ldsm_x4(uint32_t* r, uint32_t addr) {
    asm volatile("ldmatrix.sync.aligned.m8n8.x4.shared.b16 {%0,%1,%2,%3}, [%4];"
                 : "=r"(r[0]), "=r"(r[1]), "=r"(r[2]), "=r"(r[3]) : "r"(addr));
}
__device__ __forceinline__ void mma_f16(float* c, const uint32_t* a,
                                        uint32_t b0, uint32_t b1) {
    asm volatile(
        "mma.sync.aligned.m16n8k16.row.col.f32.f16.f16.f32 "
        "{%0,%1,%2,%3}, {%4,%5,%6,%7}, {%8,%9}, {%0,%1,%2,%3};"
        : "+f"(c[0]), "+f"(c[1]), "+f"(c[2]), "+f"(c[3])
        : "r"(a[0]), "r"(a[1]), "r"(a[2]), "r"(a[3]), "r"(b0), "r"(b1));
}
__device__ __forceinline__ void cp_async16(uint32_t dst, const void* src) {
    asm volatile("cp.async.cg.shared.global [%0], [%1], 16;"
                 :: "r"(dst), "l"(src) : "memory");
}
#define CP_COMMIT() asm volatile("cp.async.commit_group;" ::: "memory")
#define CP_WAIT0()  asm volatile("cp.async.wait_group 0;" ::: "memory")

__device__ __forceinline__ uint32_t pack_h2(__half a, __half b) {
    __half2 p(a, b);
    return *reinterpret_cast<uint32_t*>(&p);
}

// ---------------------------------------------------------------- prep kernel
__global__ __launch_bounds__(256)
void prep_kernel(const float* __restrict__ W, const float* __restrict__ X) {
    if (blockIdx.x < 128) {
        __shared__ float tile[32][33];
        const int bw = blockIdx.x;
        const int n0 = (bw & 15) * 32, k0 = (bw >> 4) * 32;
        const int tx = threadIdx.x & 31, ty = threadIdx.x >> 5;   // 32 x 8
        #pragma unroll
        for (int i = 0; i < 32; i += 8)
            tile[ty + i][tx] = W[(size_t)(k0 + ty + i) * U_DIM + n0 + tx];
        __syncthreads();
        #pragma unroll
        for (int i = 0; i < 32; i += 8)
            g_Wt[(size_t)(n0 + ty + i) * K_DIM + k0 + tx] =
                __float2half_rn(tile[tx][ty + i]);
    } else {
        const int bx = blockIdx.x - 128;
        #pragma unroll
        for (int i = 0; i < 8; i++) {
            size_t idx = (size_t)bx * 2048 + i * 256 + threadIdx.x;  // float4 idx
            float4 v = reinterpret_cast<const float4*>(X)[idx];
            uint2 o;
            o.x = pack_h2(__float2half_rn(v.x), __float2half_rn(v.y));
            o.y = pack_h2(__float2half_rn(v.z), __float2half_rn(v.w));
            *reinterpret_cast<uint2*>(g_Xh + idx * 4) = o;
        }
    }
}

// ---------------------------------------------------------------- fused kernel
// 256 threads = 8 warps in 4(m) x 2(n). Warp tile 32x64.
__global__ __launch_bounds__(256, 2)
void indrnn_fused_kernel(const float* __restrict__ bias,  // [N]
                         const float* __restrict__ h0g,   // [B, U]
                         const float* __restrict__ ug,    // [U]
                         float* __restrict__ C)           // out [M, U_DIM]
{
    extern __shared__ char smem[];
    const uint32_t sb = smem_u32(smem);
    float* const scf = reinterpret_cast<float*>(smem + STAGES_BYTES);
    float* const sh  = reinterpret_cast<float*>(smem + SH_OFF);
    float* const su  = reinterpret_cast<float*>(smem + SU_OFF);

    const int tid  = threadIdx.x;
    const int lane = tid & 31;
    const int wid  = tid >> 5;
    const int wm   = wid & 3;
    const int wn   = wid >> 2;
    const int n0   = blockIdx.x * NT;
    const int b    = blockIdx.y;
    const int mB   = b * T_DIM;

    // init scan state in smem (threads 0..127 own columns)
    if (tid < 128) {
        su[tid] = fminf(fmaxf(ug[n0 + tid], 0.0f), 1.0f);
        sh[tid] = h0g[(size_t)b * U_DIM + n0 + tid];
    }

    // cp.async mapping: per operand 512 x 16B, 2 per thread
    const int cRow[2] = { tid >> 2, 64 + (tid >> 2) };
    const int cC16 = tid & 3;
    // ldmatrix lane offsets
    const uint32_t aOff = (uint32_t)((lane & 15) * ROWB + (lane >> 4) * 16);
    const uint32_t bOff = (uint32_t)(((lane & 7) + ((lane >> 4) & 1) * 8) * ROWB
                                     + ((lane >> 3) & 1) * 16);
    // dump fragment coords
    const int colBase = wn * 64 + (lane & 3) * 2;
    const int rowBase = wm * 32 + (lane >> 2);

    // issue chunk ch (0..31): tile = ch>>3, k-slice = (ch&7)*KC
    auto issue_chunk = [&](int ch) {
        const uint32_t st = sb + (uint32_t)((ch & 1) * STG_B);
        const size_t mrow = (size_t)(mB + ((ch >> 3) << 7));
        const int kk = (ch & 7) * KC;
        #pragma unroll
        for (int i = 0; i < 2; i++) {
            cp_async16(st + (uint32_t)(cRow[i] * ROWB + cC16 * 16),
                       g_Xh + (mrow + cRow[i]) * K_DIM + kk + cC16 * 8);
            cp_async16(st + TSTG + (uint32_t)(cRow[i] * ROWB + cC16 * 16),
                       g_Wt + (size_t)(n0 + cRow[i]) * K_DIM + kk + cC16 * 8);
        }
        CP_COMMIT();
    };

    issue_chunk(0);

    #pragma unroll 1
    for (int tc = 0; tc < 4; tc++) {
        const int m0 = mB + tc * MT;
        const int mp = m0 - MT;           // previous tile's first row

        float acc[2][8][4];
        #pragma unroll
        for (int mt = 0; mt < 2; mt++)
            #pragma unroll
            for (int nt = 0; nt < 8; nt++)
                #pragma unroll
                for (int q = 0; q < 4; q++)
                    acc[mt][nt][q] = 0.0f;

        #pragma unroll 1
        for (int c = 0; c < 8; c++) {
            const int ch = tc * 8 + c;
            CP_WAIT0();
            __syncthreads();              // chunk ch resident; scan state coherent
            if (ch + 1 < 32) issue_chunk(ch + 1);

            // ---- MMA for chunk ch ----
            const uint32_t uA = sb + (uint32_t)((ch & 1) * STG_B);
            const uint32_t uB = uA + TSTG;
            #pragma unroll
            for (int ks = 0; ks < 2; ks++) {
                const uint32_t kb = ks * 32;
                uint32_t ah[2][4];
                #pragma unroll
                for (int mt = 0; mt < 2; mt++)
                    ldsm_x4(ah[mt], uA + (uint32_t)((wm * 32 + mt * 16) * ROWB) + aOff + kb);
                #pragma unroll
                for (int np = 0; np < 4; np++) {
                    uint32_t bh[4];
                    ldsm_x4(bh, uB + (uint32_t)((wn * 64 + np * 16) * ROWB) + bOff + kb);
                    #pragma unroll
                    for (int mt = 0; mt < 2; mt++) {
                        mma_f16(acc[mt][np * 2 + 0], ah[mt], bh[0], bh[1]);
                        mma_f16(acc[mt][np * 2 + 1], ah[mt], bh[2], bh[3]);
                    }
                }
            }

            // ---- scan slice c of PREVIOUS tile (alternating warp groups) ----
            if (tc > 0 && (wid >> 2) == (c & 1)) {
                const int col = tid - (c & 1) * 128;     // 0..127
                const int t0 = c * 16;
                float hh = sh[col];
                const float uu = su[col];
                float v[16];
                #pragma unroll
                for (int i = 0; i < 16; i++)
                    v[i] = scf[(size_t)(t0 + i) * SCROW + col];
                #pragma unroll
                for (int i = 0; i < 16; i++) {
                    hh = fmaxf(fmaf(hh, uu, v[i]), 0.0f);
                    v[i] = hh;
                }
                sh[col] = hh;
                float* crow = C + (size_t)(mp + t0) * U_DIM + n0 + col;
                #pragma unroll
                for (int i = 0; i < 16; i++)
                    crow[(size_t)i * U_DIM] = v[i];
            }
        }

        __syncthreads();   // slice reads of scf + MMA done; safe to overwrite

        // ---- dump full tile acc (+bias) into scan buffer ----
        #pragma unroll
        for (int nt = 0; nt < 8; nt++) {
            const int col = colBase + nt * 8;
            float2 bv = *reinterpret_cast<const float2*>(bias + n0 + col);
            #pragma unroll
            for (int mt = 0; mt < 2; mt++) {
                const int r = rowBase + mt * 16;
                float2 o0 = { acc[mt][nt][0] + bv.x, acc[mt][nt][1] + bv.y };
                float2 o1 = { acc[mt][nt][2] + bv.x, acc[mt][nt][3] + bv.y };
                *reinterpret_cast<float2*>(scf + (size_t)r * SCROW + col)       = o0;
                *reinterpret_cast<float2*>(scf + (size_t)(r + 8) * SCROW + col) = o1;
            }
        }
        // next tile's first chunk __syncthreads orders dump before its slices
    }

    // ---- drain: scan the last tile (tc=3) ----
    __syncthreads();
    if (tid < 128) {
        float hh = sh[tid];
        const float uu = su[tid];
        float* crow = C + (size_t)(mB + 3 * MT) * U_DIM + n0 + tid;
        #pragma unroll
        for (int t = 0; t < MT; t += 8) {
            float v[8];
            #pragma unroll
            for (int i = 0; i < 8; i++)
                v[i] = scf[(size_t)(t + i) * SCROW + tid];
            #pragma unroll
            for (int i = 0; i < 8; i++) {
                hh = fmaxf(fmaf(hh, uu, v[i]), 0.0f);
                v[i] = hh;
            }
            #pragma unroll
            for (int i = 0; i < 8; i++)
                crow[(size_t)(t + i) * U_DIM] = v[i];
        }
    }
}

// ---------------------------------------------------------------- launch
extern "C" void kernel_launch(void* const* d_in, const int* in_sizes, int n_in,
                              void* d_out, int out_size)
{
    const float* x  = (const float*)d_in[0];  // [B,T,D]
    const float* h0 = (const float*)d_in[1];  // [B,U]
    const float* W  = (const float*)d_in[2];  // [D,U]
    const float* u  = (const float*)d_in[3];  // [U]
    const float* bb = (const float*)d_in[4];  // [U]
    float* out = (float*)d_out;               // [B,T,U]

    const int U = in_sizes[3];                // 512
    const int B = in_sizes[1] / U;            // 64

    // 1) prep: W^T -> fp16, x -> fp16
    prep_kernel<<<128 + 1024, 256>>>(W, x);

    // 2) fused GEMM + pipelined scan
    cudaFuncSetAttribute(indrnn_fused_kernel,
                         cudaFuncAttributeMaxDynamicSharedMemorySize, SMEM_BYTES);
    dim3 gg(U / NT, B);   // (4, 64) = 256 CTAs, single wave at occ 2
    indrnn_fused_kernel<<<gg, 256, SMEM_BYTES>>>(bb, h0, u, out);
}

// round 13
// speedup vs baseline: 1.2416x; 1.0209x over previous
#include <cuda_runtime.h>
#include <cuda_fp16.h>
#include <cstdint>

// ============================================================================
// IndRNN on GB300 — prep v2 (bandwidth-optimized) + R8 fused GEMM/scan kernel.
//   Fused kernel identical to the measured 46.9us config: 256 threads,
//   8 warps 4(m)x2(n), 32x64 warp tiles, KC=32, 3-stage pure cp.async ring,
//   per-tile two half-tile dump+scan phases, direct coalesced STG.
//   Prep: x fp32->fp16 with 16B stores, 8 uint4/thread; W^T transpose.
// Shapes: B=64, T=512, D(K)=256, U(N)=512, M=B*T=32768
// rel_err ~ 2.35e-4 (identical fp16 roundings to R5-R12).
// ============================================================================

#define U_DIM 512
#define K_DIM 256
#define T_DIM 512
#define M_DIM 32768
#define MT 128
#define NT 128
#define KC 32
#define ROWB 80                        // 5*16: conflict-free ldmatrix
#define TSTG (128 * ROWB)              // one 128x32 fp16 tile: 10240 B
#define STG_B (2 * TSTG)               // A + B per stage: 20480 B
#define NSTAGE 3
#define STAGES_BYTES (NSTAGE * STG_B)  // 61440 B
#define SCROW 130
#define SCBYTES (64 * SCROW * 4)       // 33280 B (half tile)
#define SMEM_BYTES (STAGES_BYTES + SCBYTES)  // 94720 B -> occ 2

__device__ __half g_Wt[U_DIM * K_DIM];   // W^T [N][K] fp16
__device__ __half g_Xh[M_DIM * K_DIM];   // x   [M][K] fp16

// ---------------------------------------------------------------- helpers
__device__ __forceinline__ uint32_t smem_u32(const void* p) {
    uint32_t a;
    asm("{ .reg .u64 t; cvta.to.shared.u64 t, %1; cvt.u32.u64 %0, t; }"
        : "=r"(a) : "l"(p));
    return a;
}
__device__ __forceinline__ void ldsm_x4(uint32_t* r, uint32_t addr) {
    asm volatile("ldmatrix.sync.aligned.m8n8.x4.shared.b16 {%0,%1,%2,%3}, [%4];"
                 : "=r"(r[0]), "=r"(r[1]), "=r"(r[2]), "=r"(r[3]) : "r"(addr));
}
__device__ __forceinline__ void mma_f16(float* c, const uint32_t* a,
                                        uint32_t b0, uint32_t b1) {
    asm volatile(
        "mma.sync.aligned.m16n8k16.row.col.f32.f16.f16.f32 "
        "{%0,%1,%2,%3}, {%4,%5,%6,%7}, {%8,%9}, {%0,%1,%2,%3};"
        : "+f"(c[0]), "+f"(c[1]), "+f"(c[2]), "+f"(c[3])
        : "r"(a[0]), "r"(a[1]), "r"(a[2]), "r"(a[3]), "r"(b0), "r"(b1));
}
__device__ __forceinline__ void cp_async16(uint32_t dst, const void* src) {
    asm volatile("cp.async.cg.shared.global [%0], [%1], 16;"
                 :: "r"(dst), "l"(src) : "memory");
}
#define CP_COMMIT() asm volatile("cp.async.commit_group;" ::: "memory")
#define CP_WAIT1()  asm volatile("cp.async.wait_group 1;" ::: "memory")

__device__ __forceinline__ uint32_t pack_h2(__half a, __half b) {
    __half2 p(a, b);
    return *reinterpret_cast<uint32_t*>(&p);
}

// ---------------------------------------------------------------- prep kernel
// blocks [0,128): W^T transpose. blocks [128,640): x fp32 -> fp16, 16B stores.
__global__ __launch_bounds__(256)
void prep_kernel(const float* __restrict__ W, const float* __restrict__ X) {
    if (blockIdx.x < 128) {
        __shared__ float tile[32][33];
        const int bw = blockIdx.x;
        const int n0 = (bw & 15) * 32, k0 = (bw >> 4) * 32;
        const int tx = threadIdx.x & 31, ty = threadIdx.x >> 5;   // 32 x 8
        #pragma unroll
        for (int i = 0; i < 32; i += 8)
            tile[ty + i][tx] = W[(size_t)(k0 + ty + i) * U_DIM + n0 + tx];
        __syncthreads();
        #pragma unroll
        for (int i = 0; i < 32; i += 8)
            g_Wt[(size_t)(n0 + ty + i) * K_DIM + k0 + tx] =
                __float2half_rn(tile[tx][ty + i]);
    } else {
        // 512 blocks x 256 threads x 8 uint4-out = 1,048,576 x 16B = 16 MB out.
        // Each output uint4 = 8 halves = two input float4 (32 B in).
        const uint32_t g = (blockIdx.x - 128) * 256 + threadIdx.x;  // 0..131071
        const float4* xin = reinterpret_cast<const float4*>(X);
        uint4* xout = reinterpret_cast<uint4*>(g_Xh);
        #pragma unroll
        for (int i = 0; i < 8; i++) {
            size_t o = (size_t)i * 131072 + g;          // grid-strided, coalesced
            float4 v0 = xin[o * 2];
            float4 v1 = xin[o * 2 + 1];
            uint4 r;
            r.x = pack_h2(__float2half_rn(v0.x), __float2half_rn(v0.y));
            r.y = pack_h2(__float2half_rn(v0.z), __float2half_rn(v0.w));
            r.z = pack_h2(__float2half_rn(v1.x), __float2half_rn(v1.y));
            r.w = pack_h2(__float2half_rn(v1.z), __float2half_rn(v1.w));
            xout[o] = r;
        }
    }
}

// ---------------------------------------------------------------- fused kernel
// IDENTICAL to the measured 46.9us R8 kernel.
// 256 threads = 8 warps in 4(m) x 2(n). Warp tile 32x64.
__global__ __launch_bounds__(256, 2)
void indrnn_fused_kernel(const float* __restrict__ bias,  // [N]
                         const float* __restrict__ h0g,   // [B, U]
                         const float* __restrict__ ug,    // [U]
                         float* __restrict__ C)           // out [M, U_DIM]
{
    extern __shared__ char smem[];
    const uint32_t sb = smem_u32(smem);
    float* const scf = reinterpret_cast<float*>(smem + STAGES_BYTES);

    const int tid  = threadIdx.x;
    const int lane = tid & 31;
    const int wid  = tid >> 5;
    const int wm   = wid & 3;
    const int wn   = wid >> 2;
    const int n0   = blockIdx.x * NT;
    const int b    = blockIdx.y;
    const int mB   = b * T_DIM;

    // scan state: thread tid<128 owns column n0+tid
    float h = 0.0f, uc = 0.0f;
    if (tid < 128) {
        uc = fminf(fmaxf(ug[n0 + tid], 0.0f), 1.0f);
        h  = h0g[(size_t)b * U_DIM + n0 + tid];
    }

    // cp.async mapping: per operand 512 x 16B, 2 per thread
    const int cRow[2] = { (0*256 + tid) >> 2, (1*256 + tid) >> 2 };
    const int cC16 = tid & 3;
    // ldmatrix lane offsets
    const uint32_t aOff = (uint32_t)((lane & 15) * ROWB + (lane >> 4) * 16);
    const uint32_t bOff = (uint32_t)(((lane & 7) + ((lane >> 4) & 1) * 8) * ROWB
                                     + ((lane >> 3) & 1) * 16);
    // dump fragment coords
    const int colBase = wn * 64 + (lane & 3) * 2;
    const int rowBase = wm * 32 + (lane >> 2);

    // issue chunk ch (0..31): tile = ch>>3, k-slice = (ch&7)*KC
    auto issue_chunk = [&](int ch) {
        const uint32_t st = sb + (uint32_t)((ch % NSTAGE) * STG_B);
        const size_t mrow = (size_t)(mB + ((ch >> 3) << 7));
        const int kk = (ch & 7) * KC;
        #pragma unroll
        for (int i = 0; i < 2; i++) {
            cp_async16(st + (uint32_t)(cRow[i] * ROWB + cC16 * 16),
                       g_Xh + (mrow + cRow[i]) * K_DIM + kk + cC16 * 8);
            cp_async16(st + TSTG + (uint32_t)(cRow[i] * ROWB + cC16 * 16),
                       g_Wt + (size_t)(n0 + cRow[i]) * K_DIM + kk + cC16 * 8);
        }
        CP_COMMIT();
    };

    issue_chunk(0);
    issue_chunk(1);

    #pragma unroll 1
    for (int tc = 0; tc < T_DIM / MT; tc++) {
        const int m0 = mB + tc * MT;

        float acc[2][8][4];
        #pragma unroll
        for (int mt = 0; mt < 2; mt++)
            #pragma unroll
            for (int nt = 0; nt < 8; nt++)
                #pragma unroll
                for (int q = 0; q < 4; q++)
                    acc[mt][nt][q] = 0.0f;

        #pragma unroll 1
        for (int c = 0; c < 8; c++) {
            const int ch = tc * 8 + c;
            CP_WAIT1();
            __syncthreads();            // chunk ch resident; stage (ch+2)%3 free
            if (ch + 2 < 32) issue_chunk(ch + 2);

            const uint32_t uA = sb + (uint32_t)((ch % NSTAGE) * STG_B);
            const uint32_t uB = uA + TSTG;
            #pragma unroll
            for (int ks = 0; ks < 2; ks++) {
                const uint32_t kb = ks * 32;
                uint32_t ah[2][4];
                #pragma unroll
                for (int mt = 0; mt < 2; mt++)
                    ldsm_x4(ah[mt], uA + (uint32_t)((wm * 32 + mt * 16) * ROWB) + aOff + kb);
                #pragma unroll
                for (int np = 0; np < 4; np++) {
                    uint32_t bh[4];
                    ldsm_x4(bh, uB + (uint32_t)((wn * 64 + np * 16) * ROWB) + bOff + kb);
                    #pragma unroll
                    for (int mt = 0; mt < 2; mt++) {
                        mma_f16(acc[mt][np * 2 + 0], ah[mt], bh[0], bh[1]);
                        mma_f16(acc[mt][np * 2 + 1], ah[mt], bh[2], bh[3]);
                    }
                }
            }
        }

        // ---- two half-tile dump+scan phases (rows p*64 .. p*64+63) ----
        #pragma unroll 1
        for (int p = 0; p < 2; p++) {
            __syncthreads();   // prev phase's scan reads done
            if ((wm >> 1) == p) {
                const int rloc = rowBase - p * 64;   // 0..63 for owning warps
                #pragma unroll
                for (int nt = 0; nt < 8; nt++) {
                    const int col = colBase + nt * 8;
                    float2 bv = *reinterpret_cast<const float2*>(bias + n0 + col);
                    #pragma unroll
                    for (int mt = 0; mt < 2; mt++) {
                        const int r = rloc + mt * 16;
                        float2 o0 = { acc[mt][nt][0] + bv.x, acc[mt][nt][1] + bv.y };
                        float2 o1 = { acc[mt][nt][2] + bv.x, acc[mt][nt][3] + bv.y };
                        *reinterpret_cast<float2*>(scf + (size_t)r * SCROW + col)       = o0;
                        *reinterpret_cast<float2*>(scf + (size_t)(r + 8) * SCROW + col) = o1;
                    }
                }
            }
            __syncthreads();
            if (tid < 128) {
                float* crow = C + (size_t)(m0 + p * 64) * U_DIM + n0 + tid;
                #pragma unroll
                for (int t = 0; t < 64; t += 8) {
                    float v[8];
                    #pragma unroll
                    for (int i = 0; i < 8; i++)
                        v[i] = scf[(size_t)(t + i) * SCROW + tid];
                    #pragma unroll
                    for (int i = 0; i < 8; i++) {
                        h = fmaxf(fmaf(h, uc, v[i]), 0.0f);
                        v[i] = h;
                    }
                    #pragma unroll
                    for (int i = 0; i < 8; i++)
                        crow[(size_t)(t + i) * U_DIM] = v[i];
                }
            }
        }
        __syncthreads();    // scan reads done before next tile's dump
    }
}

// ---------------------------------------------------------------- launch
extern "C" void kernel_launch(void* const* d_in, const int* in_sizes, int n_in,
                              void* d_out, int out_size)
{
    const float* x  = (const float*)d_in[0];  // [B,T,D]
    const float* h0 = (const float*)d_in[1];  // [B,U]
    const float* W  = (const float*)d_in[2];  // [D,U]
    const float* u  = (const float*)d_in[3];  // [U]
    const float* bb = (const float*)d_in[4];  // [U]
    float* out = (float*)d_out;               // [B,T,U]

    const int U = in_sizes[3];                // 512
    const int B = in_sizes[1] / U;            // 64

    // 1) prep: W^T -> fp16 (128 blocks), x -> fp16 (512 blocks, 16B stores)
    prep_kernel<<<128 + 512, 256>>>(W, x);

    // 2) fused GEMM + scan (identical to the 46.9us R8 kernel)
    cudaFuncSetAttribute(indrnn_fused_kernel,
                         cudaFuncAttributeMaxDynamicSharedMemorySize, SMEM_BYTES);
    dim3 gg(U / NT, B);   // (4, 64) = 256 CTAs, single wave at occ 2
    indrnn_fused_kernel<<<gg, 256, SMEM_BYTES>>>(bb, h0, u, out);
}

// round 14
// speedup vs baseline: 1.3591x; 1.0947x over previous
#include <cuda_runtime.h>
#include <cuda_fp16.h>
#include <cstdint>

// ============================================================================
// IndRNN on GB300 — ONE kernel, NO device scratch:
//   Prologue per CTA: convert W n-block (fp32, L2-hot) -> resident B in smem
//   (fp16, XOR-swizzled unpadded 64B rows, conflict-free ldmatrix).
//   Mainloop: A-only pipeline (coalesced LDG fp32 -> cvt fp16 -> STS,
//   2-stage ring, 1 sync/chunk), 16 HMMA per warp per chunk.
//   Per 128-row tile: two half-tile dump+scan phases (R8 code), scan state in
//   registers, direct coalesced STG.
// Shapes: B=64, T=512, D(K)=256, U(N)=512, M=B*T=32768
// rel_err ~ 2.35e-4 (identical fp16 roundings to R5-R13).
// ============================================================================

#define U_DIM 512
#define K_DIM 256
#define T_DIM 512
#define MT 128
#define NT 128
#define KC 32
// swizzled unpadded layouts: row stride 64B; chunk c at ((c ^ ((r>>1)&3))<<4)
#define B_BASE 0                       // 8 subtiles x 8192 = 65536 B
#define A_BASE 65536                   // 2 stages x 8192 = 16384 B
#define SC_BASE (65536 + 16384)        // scan buffer
#define SCROW 130
#define SCBYTES (64 * SCROW * 4)       // 33280 B (half tile)
#define SMEM_BYTES (SC_BASE + SCBYTES) // 115200 B -> occ 2 (230400 <= 233472)

// ---------------------------------------------------------------- helpers
__device__ __forceinline__ uint32_t smem_u32(const void* p) {
    uint32_t a;
    asm("{ .reg .u64 t; cvta.to.shared.u64 t, %1; cvt.u32.u64 %0, t; }"
        : "=r"(a) : "l"(p));
    return a;
}
__device__ __forceinline__ void ldsm_x4(uint32_t* r, uint32_t addr) {
    asm volatile("ldmatrix.sync.aligned.m8n8.x4.shared.b16 {%0,%1,%2,%3}, [%4];"
                 : "=r"(r[0]), "=r"(r[1]), "=r"(r[2]), "=r"(r[3]) : "r"(addr));
}
__device__ __forceinline__ void mma_f16(float* c, const uint32_t* a,
                                        uint32_t b0, uint32_t b1) {
    asm volatile(
        "mma.sync.aligned.m16n8k16.row.col.f32.f16.f16.f32 "
        "{%0,%1,%2,%3}, {%4,%5,%6,%7}, {%8,%9}, {%0,%1,%2,%3};"
        : "+f"(c[0]), "+f"(c[1]), "+f"(c[2]), "+f"(c[3])
        : "r"(a[0]), "r"(a[1]), "r"(a[2]), "r"(a[3]), "r"(b0), "r"(b1));
}
__device__ __forceinline__ uint32_t pack_h2(__half a, __half b) {
    __half2 p(a, b);
    return *reinterpret_cast<uint32_t*>(&p);
}
__device__ __forceinline__ void sts8(uint32_t dst, uint32_t v0, uint32_t v1) {
    asm volatile("st.shared.v2.b32 [%0], {%1, %2};"
                 :: "r"(dst), "r"(v0), "r"(v1) : "memory");
}
__device__ __forceinline__ void sts16(uint32_t dst, uint4 v) {
    asm volatile("st.shared.v4.b32 [%0], {%1,%2,%3,%4};"
                 :: "r"(dst), "r"(v.x), "r"(v.y), "r"(v.z), "r"(v.w) : "memory");
}

// ---------------------------------------------------------------- kernel
// 256 threads = 8 warps in 4(m) x 2(n). Warp tile 32x64.
__global__ __launch_bounds__(256, 2)
void indrnn_one_kernel(const float* __restrict__ W,     // [K, N] fp32
                       const float* __restrict__ X,     // [M, K] fp32
                       const float* __restrict__ bias,  // [N]
                       const float* __restrict__ h0g,   // [B, U]
                       const float* __restrict__ ug,    // [U]
                       float* __restrict__ C)           // [M, U_DIM]
{
    extern __shared__ char smem[];
    const uint32_t sb = smem_u32(smem);
    float* const scf = reinterpret_cast<float*>(smem + SC_BASE);

    const int tid  = threadIdx.x;
    const int lane = tid & 31;
    const int wid  = tid >> 5;
    const int wm   = wid & 3;
    const int wn   = wid >> 2;
    const int n0   = blockIdx.x * NT;
    const int b    = blockIdx.y;
    const int mB   = b * T_DIM;

    // scan state: thread tid<128 owns column n0+tid
    float h = 0.0f, uc = 0.0f;
    if (tid < 128) {
        uc = fminf(fmaxf(ug[n0 + tid], 0.0f), 1.0f);
        h  = h0g[(size_t)b * U_DIM + n0 + tid];
    }

    // ---------------- prologue: resident B = W^T fp16, swizzled ----------------
    // thread: n-row r = tid>>1, k-half hh = tid&1 (4 subtiles of 32 k each)
    {
        const int r  = tid >> 1;
        const int hh = tid & 1;
        const uint32_t mrow = ((uint32_t)(r >> 1)) & 3;
        #pragma unroll
        for (int s4 = 0; s4 < 4; s4++) {
            const int sc = hh * 4 + s4;          // subtile 0..7
            const int k0 = sc * 32;
            float v[32];
            #pragma unroll
            for (int k = 0; k < 32; k++)
                v[k] = W[(size_t)(k0 + k) * U_DIM + n0 + r];
            #pragma unroll
            for (int cc = 0; cc < 4; cc++) {
                uint4 q;
                q.x = pack_h2(__float2half_rn(v[cc*8+0]), __float2half_rn(v[cc*8+1]));
                q.y = pack_h2(__float2half_rn(v[cc*8+2]), __float2half_rn(v[cc*8+3]));
                q.z = pack_h2(__float2half_rn(v[cc*8+4]), __float2half_rn(v[cc*8+5]));
                q.w = pack_h2(__float2half_rn(v[cc*8+6]), __float2half_rn(v[cc*8+7]));
                sts16(sb + B_BASE + (uint32_t)(sc * 8192 + r * 64)
                         + (((uint32_t)cc ^ mrow) << 4), q);
            }
        }
    }

    // A mappings (coalesced LDG, swizzled STS)
    const int aRowT = tid >> 3;                  // 0..31 (row within i-group)
    const int c4    = tid & 7;                   // float4 column
    const uint32_t mA_sts = ((uint32_t)(aRowT >> 1)) & 3;
    const uint32_t aStsOff = (uint32_t)(aRowT * 64)
        + ((((uint32_t)(c4 >> 1)) ^ mA_sts) << 4) + (uint32_t)((c4 & 1) * 8);

    // ldmatrix lane offsets (swizzled)
    const uint32_t mA = (((uint32_t)(lane & 15)) >> 1) & 3;
    const uint32_t aOff = (uint32_t)((lane & 15) * 64)
        + ((((uint32_t)(lane >> 4)) ^ mA) << 4);
    const uint32_t mBs = (((uint32_t)(lane & 7)) >> 1) & 3;
    const uint32_t bOff = (uint32_t)(((lane & 7) + ((lane >> 4) & 1) * 8) * 64)
        + ((((uint32_t)((lane >> 3) & 1)) ^ mBs) << 4);

    // dump fragment coords
    const int colBase = wn * 64 + (lane & 3) * 2;
    const int rowBase = wm * 32 + (lane >> 2);

    float4 rA[4];
    auto ldg_chunk = [&](int ch) {
        const size_t mrow = (size_t)(mB + ((ch >> 3) << 7));
        const int kk = (ch & 7) * KC;
        #pragma unroll
        for (int i = 0; i < 4; i++)
            rA[i] = *reinterpret_cast<const float4*>(
                X + (mrow + i * 32 + aRowT) * K_DIM + kk + c4 * 4);
    };
    auto sts_chunk = [&](int ch) {
        const uint32_t st = sb + (uint32_t)(A_BASE + (ch & 1) * 8192);
        #pragma unroll
        for (int i = 0; i < 4; i++) {
            __half hx = __float2half_rn(rA[i].x), hy = __float2half_rn(rA[i].y);
            __half hz = __float2half_rn(rA[i].z), hw = __float2half_rn(rA[i].w);
            sts8(st + (uint32_t)(i * 2048) + aStsOff,
                 pack_h2(hx, hy), pack_h2(hz, hw));
        }
    };

    // prologue for A: chunk 0
    ldg_chunk(0);
    sts_chunk(0);

    #pragma unroll 1
    for (int tc = 0; tc < 4; tc++) {
        const int m0 = mB + tc * MT;

        float acc[2][8][4];
        #pragma unroll
        for (int mt = 0; mt < 2; mt++)
            #pragma unroll
            for (int nt = 0; nt < 8; nt++)
                #pragma unroll
                for (int q = 0; q < 4; q++)
                    acc[mt][nt][q] = 0.0f;

        #pragma unroll 1
        for (int c = 0; c < 8; c++) {
            const int ch = tc * 8 + c;
            if (ch + 1 < 32) ldg_chunk(ch + 1);     // overlap with compute
            __syncthreads();                         // stage ch&1 visible to all

            const uint32_t uA = sb + (uint32_t)(A_BASE + (ch & 1) * 8192)
                                   + (uint32_t)(wm * 2048);
            const uint32_t uB = sb + (uint32_t)(B_BASE + (ch & 7) * 8192)
                                   + (uint32_t)(wn * 4096);
            #pragma unroll
            for (int ks = 0; ks < 2; ks++) {
                const uint32_t kx = ks ? 0x20u : 0u;
                uint32_t ah[2][4];
                #pragma unroll
                for (int mt = 0; mt < 2; mt++)
                    ldsm_x4(ah[mt], (uA + (uint32_t)(mt * 1024) + aOff) ^ kx);
                #pragma unroll
                for (int np = 0; np < 4; np++) {
                    uint32_t bh[4];
                    ldsm_x4(bh, (uB + (uint32_t)(np * 1024) + bOff) ^ kx);
                    #pragma unroll
                    for (int mt = 0; mt < 2; mt++) {
                        mma_f16(acc[mt][np * 2 + 0], ah[mt], bh[0], bh[1]);
                        mma_f16(acc[mt][np * 2 + 1], ah[mt], bh[2], bh[3]);
                    }
                }
            }
            if (ch + 1 < 32) sts_chunk(ch + 1);     // other stage; safe post-sync
        }

        // ---- two half-tile dump+scan phases (rows p*64 .. p*64+63) ----
        #pragma unroll 1
        for (int p = 0; p < 2; p++) {
            __syncthreads();   // prev phase's scan reads done
            if ((wm >> 1) == p) {
                const int rloc = rowBase - p * 64;   // 0..63 for owning warps
                #pragma unroll
                for (int nt = 0; nt < 8; nt++) {
                    const int col = colBase + nt * 8;
                    float2 bv = *reinterpret_cast<const float2*>(bias + n0 + col);
                    #pragma unroll
                    for (int mt = 0; mt < 2; mt++) {
                        const int r = rloc + mt * 16;
                        float2 o0 = { acc[mt][nt][0] + bv.x, acc[mt][nt][1] + bv.y };
                        float2 o1 = { acc[mt][nt][2] + bv.x, acc[mt][nt][3] + bv.y };
                        *reinterpret_cast<float2*>(scf + (size_t)r * SCROW + col)       = o0;
                        *reinterpret_cast<float2*>(scf + (size_t)(r + 8) * SCROW + col) = o1;
                    }
                }
            }
            __syncthreads();
            if (tid < 128) {
                float* crow = C + (size_t)(m0 + p * 64) * U_DIM + n0 + tid;
                #pragma unroll
                for (int t = 0; t < 64; t += 8) {
                    float v[8];
                    #pragma unroll
                    for (int i = 0; i < 8; i++)
                        v[i] = scf[(size_t)(t + i) * SCROW + tid];
                    #pragma unroll
                    for (int i = 0; i < 8; i++) {
                        h = fmaxf(fmaf(h, uc, v[i]), 0.0f);
                        v[i] = h;
                    }
                    #pragma unroll
                    for (int i = 0; i < 8; i++)
                        crow[(size_t)(t + i) * U_DIM] = v[i];
                }
            }
        }
        __syncthreads();    // scan reads done before next tile's dump
    }
}

// ---------------------------------------------------------------- launch
extern "C" void kernel_launch(void* const* d_in, const int* in_sizes, int n_in,
                              void* d_out, int out_size)
{
    const float* x  = (const float*)d_in[0];  // [B,T,D]
    const float* h0 = (const float*)d_in[1];  // [B,U]
    const float* W  = (const float*)d_in[2];  // [D,U]
    const float* u  = (const float*)d_in[3];  // [U]
    const float* bb = (const float*)d_in[4];  // [U]
    float* out = (float*)d_out;               // [B,T,U]

    const int U = in_sizes[3];                // 512
    const int B = in_sizes[1] / U;            // 64

    cudaFuncSetAttribute(indrnn_one_kernel,
                         cudaFuncAttributeMaxDynamicSharedMemorySize, SMEM_BYTES);
    dim3 gg(U / NT, B);   // (4, 64) = 256 CTAs, single wave at occ 2
    indrnn_one_kernel<<<gg, 256, SMEM_BYTES>>>(W, x, bb, h0, u, out);
}